// round 1
// baseline (speedup 1.0000x reference)
#include <cuda_runtime.h>

#define DEG2RAD 0.017453292519943295f
#define EARTH_R 6371.009f

#define NBLOCKS 2048
#define NTHREADS 256

__device__ float g_partials[NBLOCKS];

// Great-circle central angle for one (pred,true,site) row.
// Longitude means/site cancel in the delta, so only the y-difference matters.
__device__ __forceinline__ float gd_angle(float p_lat, float p_lng,
                                          float t_lat, float t_lng,
                                          float s_lat,
                                          float ms0, float ss0, float kd,
                                          float m0, float sd0)
{
    float site_lat = fmaf(s_lat, sd0, m0);
    float plat = fmaf(p_lat, ss0, ms0) + site_lat;
    float tlat = fmaf(t_lat, ss0, ms0) + site_lat;
    plat = fminf(fmaxf(plat, -90.0f), 90.0f);   // clamp predicted latitude only
    float lat1 = plat * DEG2RAD;
    float lat2 = tlat * DEG2RAD;
    float delta = (t_lng - p_lng) * kd;         // (lng2-lng1) in radians, exact cancellation

    float s1, c1, s2, c2, sd, cd;
    __sincosf(lat1, &s1, &c1);
    __sincosf(lat2, &s2, &c2);
    __sincosf(delta, &sd, &cd);

    float a = c2 * sd;
    float b = fmaf(c1, s2, -(s1 * c2) * cd);    // cos1*sin2 - sin1*cos2*cosd
    float num = sqrtf(fmaf(a, a, b * b));
    float den = fmaf(s1, s2, (c1 * c2) * cd);
    return atan2f(num, den);                    // central angle sigma
}

__global__ void __launch_bounds__(NTHREADS)
gd_main(const float4* __restrict__ pred,
        const float4* __restrict__ tru,
        const float4* __restrict__ site,
        const float* __restrict__ mean_speed,
        const float* __restrict__ std_speed,
        const float* __restrict__ mean,
        const float* __restrict__ stdv,
        int n4)
{
    const float ms0 = __ldg(&mean_speed[0]);
    const float ss0 = __ldg(&std_speed[0]);
    const float kd  = __ldg(&std_speed[1]) * DEG2RAD;
    const float m0  = __ldg(&mean[0]);
    const float sd0 = __ldg(&stdv[0]);

    float acc = 0.0f;
    int idx = blockIdx.x * blockDim.x + threadIdx.x;
    int stride = gridDim.x * blockDim.x;

    for (int i = idx; i < n4; i += stride) {
        float4 p = __ldg(&pred[i]);
        float4 t = __ldg(&tru[i]);
        float4 s = __ldg(&site[i]);
        acc += gd_angle(p.x, p.y, t.x, t.y, s.x, ms0, ss0, kd, m0, sd0);
        acc += gd_angle(p.z, p.w, t.z, t.w, s.z, ms0, ss0, kd, m0, sd0);
    }

    // warp reduce
    #pragma unroll
    for (int o = 16; o > 0; o >>= 1)
        acc += __shfl_xor_sync(0xffffffffu, acc, o);

    __shared__ float sm[NTHREADS / 32];
    int lane = threadIdx.x & 31;
    int warp = threadIdx.x >> 5;
    if (lane == 0) sm[warp] = acc;
    __syncthreads();
    if (threadIdx.x == 0) {
        float v = 0.0f;
        #pragma unroll
        for (int w = 0; w < NTHREADS / 32; w++) v += sm[w];
        g_partials[blockIdx.x] = v;
    }
}

__global__ void gd_reduce(float* __restrict__ out, float scale)
{
    __shared__ float sm[8];
    int tid = threadIdx.x;  // 256 threads
    float v = 0.0f;
    #pragma unroll
    for (int i = tid; i < NBLOCKS; i += 256) v += g_partials[i];
    #pragma unroll
    for (int o = 16; o > 0; o >>= 1)
        v += __shfl_xor_sync(0xffffffffu, v, o);
    if ((tid & 31) == 0) sm[tid >> 5] = v;
    __syncthreads();
    if (tid < 8) {
        v = sm[tid];
        #pragma unroll
        for (int o = 4; o > 0; o >>= 1)
            v += __shfl_xor_sync(0xffu, v, o);
        if (tid == 0) out[0] = v * scale;
    }
}

extern "C" void kernel_launch(void* const* d_in, const int* in_sizes, int n_in,
                              void* d_out, int out_size)
{
    const float4* pred = (const float4*)d_in[0];
    const float4* tru  = (const float4*)d_in[1];
    const float*  ms   = (const float*)d_in[2];
    const float*  ss   = (const float*)d_in[3];
    const float4* site = (const float4*)d_in[4];
    const float*  mn   = (const float*)d_in[5];
    const float*  sd   = (const float*)d_in[6];

    int n4 = in_sizes[0] / 4;                 // float4 count (2 rows each)
    long long B = (long long)in_sizes[0] / 2; // row count

    gd_main<<<NBLOCKS, NTHREADS>>>(pred, tru, site, ms, ss, mn, sd, n4);

    float scale = (float)((double)EARTH_R / (double)B);
    gd_reduce<<<1, 256>>>((float*)d_out, scale);
}

// round 2
// speedup vs baseline: 1.0553x; 1.0553x over previous
#include <cuda_runtime.h>

#define DEG2RAD  0.017453292519943295f
#define PI_F     3.14159265358979323846f
#define PIO2_F   1.57079632679489661923f
#define EARTH_R  6371.009f

#define NBLOCKS  1184    // 148 SMs * 8 CTAs -> exactly one wave
#define NTHREADS 256

__device__ float g_partials[NBLOCKS];
__device__ unsigned int g_count = 0;

// atan2(num, den) for num >= 0, result in [0, pi].
// Octant reduction + degree-11 odd minimax polynomial (abs err ~2e-7 on [0,1]).
__device__ __forceinline__ float fast_atan2_pos(float num, float den)
{
    float ax = fabsf(den);
    float mn = fminf(num, ax);
    float mx = fmaxf(fmaxf(num, ax), 1e-30f);   // guard mx==0
    float z  = __fdividef(mn, mx);
    float z2 = z * z;
    float p = -0.0117212f;
    p = fmaf(p, z2,  0.05265332f);
    p = fmaf(p, z2, -0.11643287f);
    p = fmaf(p, z2,  0.19354346f);
    p = fmaf(p, z2, -0.33262347f);
    p = fmaf(p, z2,  0.99997726f);
    float a = z * p;
    if (num > ax)  a = PIO2_F - a;   // |y| > |x| octant
    if (den < 0.f) a = PI_F - a;     // left half-plane
    return a;
}

// Great-circle central angle for one row. Longitude means/site cancel in the
// delta, so only (true_lng - pred_lng)*std_speed[1] survives.
__device__ __forceinline__ float gd_angle(float p_lat, float p_lng,
                                          float t_lat, float t_lng,
                                          float s_lat,
                                          float ms0, float ss0, float kd,
                                          float m0, float sd0)
{
    float site_lat = fmaf(s_lat, sd0, m0);
    float plat = fmaf(p_lat, ss0, ms0) + site_lat;
    float tlat = fmaf(t_lat, ss0, ms0) + site_lat;
    plat = fminf(fmaxf(plat, -90.0f), 90.0f);   // clamp predicted latitude only
    float lat1 = plat * DEG2RAD;
    float lat2 = tlat * DEG2RAD;
    float delta = (t_lng - p_lng) * kd;

    float s1, c1, s2, c2, sd, cd;
    __sincosf(lat1, &s1, &c1);
    __sincosf(lat2, &s2, &c2);
    __sincosf(delta, &sd, &cd);

    float a = c2 * sd;
    float b = fmaf(c1, s2, -(s1 * c2) * cd);
    float num = sqrtf(fmaf(a, a, b * b));
    float den = fmaf(s1, s2, (c1 * c2) * cd);
    return fast_atan2_pos(num, den);
}

__global__ void __launch_bounds__(NTHREADS)
gd_fused(const float4* __restrict__ pred,
         const float4* __restrict__ tru,
         const float4* __restrict__ site,
         const float* __restrict__ mean_speed,
         const float* __restrict__ std_speed,
         const float* __restrict__ mean,
         const float* __restrict__ stdv,
         int n4, float scale, float* __restrict__ out)
{
    const float ms0 = __ldg(&mean_speed[0]);
    const float ss0 = __ldg(&std_speed[0]);
    const float kd  = __ldg(&std_speed[1]) * DEG2RAD;
    const float m0  = __ldg(&mean[0]);
    const float sd0 = __ldg(&stdv[0]);

    float acc = 0.0f;
    int idx = blockIdx.x * blockDim.x + threadIdx.x;
    int stride = gridDim.x * blockDim.x;

    for (int i = idx; i < n4; i += stride) {
        float4 p = __ldg(&pred[i]);
        float4 t = __ldg(&tru[i]);
        float4 s = __ldg(&site[i]);
        acc += gd_angle(p.x, p.y, t.x, t.y, s.x, ms0, ss0, kd, m0, sd0);
        acc += gd_angle(p.z, p.w, t.z, t.w, s.z, ms0, ss0, kd, m0, sd0);
    }

    // intra-block reduce
    #pragma unroll
    for (int o = 16; o > 0; o >>= 1)
        acc += __shfl_xor_sync(0xffffffffu, acc, o);

    __shared__ float sm[NTHREADS / 32];
    __shared__ bool is_last;
    int lane = threadIdx.x & 31;
    int warp = threadIdx.x >> 5;
    if (lane == 0) sm[warp] = acc;
    __syncthreads();

    if (threadIdx.x == 0) {
        float v = 0.0f;
        #pragma unroll
        for (int w = 0; w < NTHREADS / 32; w++) v += sm[w];
        g_partials[blockIdx.x] = v;
        __threadfence();
        unsigned int ticket = atomicAdd(&g_count, 1u);
        is_last = (ticket == gridDim.x - 1);
        if (is_last) g_count = 0;   // reset for next graph replay
    }
    __syncthreads();

    // last block: deterministic final reduction over g_partials
    if (is_last) {
        float v = 0.0f;
        for (int i = threadIdx.x; i < NBLOCKS; i += NTHREADS)
            v += g_partials[i];
        #pragma unroll
        for (int o = 16; o > 0; o >>= 1)
            v += __shfl_xor_sync(0xffffffffu, v, o);
        if (lane == 0) sm[warp] = v;
        __syncthreads();
        if (threadIdx.x == 0) {
            float t = 0.0f;
            #pragma unroll
            for (int w = 0; w < NTHREADS / 32; w++) t += sm[w];
            out[0] = t * scale;
        }
    }
}

extern "C" void kernel_launch(void* const* d_in, const int* in_sizes, int n_in,
                              void* d_out, int out_size)
{
    const float4* pred = (const float4*)d_in[0];
    const float4* tru  = (const float4*)d_in[1];
    const float*  ms   = (const float*)d_in[2];
    const float*  ss   = (const float*)d_in[3];
    const float4* site = (const float4*)d_in[4];
    const float*  mn   = (const float*)d_in[5];
    const float*  sd   = (const float*)d_in[6];

    int n4 = in_sizes[0] / 4;                 // float4 count (2 rows each)
    long long B = (long long)in_sizes[0] / 2; // row count
    float scale = (float)((double)EARTH_R / (double)B);

    gd_fused<<<NBLOCKS, NTHREADS>>>(pred, tru, site, ms, ss, mn, sd,
                                    n4, scale, (float*)d_out);
}